// round 16
// baseline (speedup 1.0000x reference)
#include <cuda_runtime.h>
#include <cuda_bf16.h>
#include <cstdint>

// out[b,s,d] = keep ? (emb[x[b,s],d] + pe[s,d]) * (1/0.9) : 0
// keep from JAX threefry2x32 (partitionable): key=(0,42), ctr=(0,i),
// bits = out0^out1, keep <=> bits < 0xE6666600  (== u<0.9f exactly)
//
// All rounds use SHF rotates (3 true issue slots/round; IMAD.WIDE rotates
// cost 4 — measured slower in R3/R5/R12/R15).
// 8 interleaved chains (2 batches x 4 lanes) give 24 independent instrs per
// 12-15 cyc dependent hop, keeping warps eligible.

#define KS1 42u
#define KS2 0x1BD11BF0u

// Shift round on 8 interleaved chains with x0-side key injection folded in:
//   IADD3(flex) + SHF(alu) + LOP3(alu)
#define S8C(rr, c01)                                                       \
    _Pragma("unroll") for (int k = 0; k < 8; k++) {                        \
        x0[k] = x0[k] + x1[k] + (c01);                                     \
        x1[k] = __funnelshift_l(x1[k], x1[k], (rr)) ^ x0[k];               \
    }

#define S8(rr) S8C(rr, 0u)

// x1-side key injection
#define INJ8(c1)                                                           \
    _Pragma("unroll") for (int k = 0; k < 8; k++) { x1[k] += (c1); }

// Chains 0-3: ctr = jA+k ; chains 4-7: ctr = jB+(k-4)
__device__ __forceinline__ void tf_bits8(uint32_t jA, uint32_t jB,
                                         uint32_t* bits) {
    uint32_t x0[8], x1[8];
    // Round-1 specialization: x0 pre-add is 0, so post-add x0 == x1_init.
#pragma unroll
    for (int k = 0; k < 8; k++) {
        const uint32_t c = (k < 4) ? (jA + (uint32_t)k)
                                   : (jB + (uint32_t)(k - 4));
        x1[k] = c + KS1;
        x0[k] = x1[k];
        x1[k] = __funnelshift_l(x1[k], x1[k], 13) ^ x0[k];
    }
    S8(15) S8(26) S8(6)
    INJ8(KS2 + 1u)
    S8C(17, KS1) S8(29) S8(16) S8(24)      // x0 += ks1 folded
    INJ8(2u)                                // ks0 == 0
    S8C(13, KS2) S8(15) S8(26) S8(6)       // x0 += ks2 folded
    INJ8(KS1 + 3u)
    S8(17) S8(29) S8(16) S8(24)            // x0 += ks0 == 0
    INJ8(KS2 + 4u)
    S8C(13, KS1) S8(15) S8(26) S8(6)       // x0 += ks1 folded
#pragma unroll
    for (int k = 0; k < 8; k++) bits[k] = (x0[k] + KS2) ^ (x1[k] + 5u);
}

// E = 8 elems/thread: 4 d-values x 2 batches (6.9 waves, 1.4% tail).
// blockIdx.x = s*8 + half*4 + bp   (bp selects batch pair {2bp, 2bp+1})
__global__ __launch_bounds__(128, 8) void embed_pe_drop_kernel(
    const int* __restrict__ x,
    const float* __restrict__ emb,
    float* __restrict__ out)
{
    const uint32_t bp   = blockIdx.x & 3u;          // batch pair 0..3
    const uint32_t half = (blockIdx.x >> 2) & 1u;   // d half
    const uint32_t s    = blockIdx.x >> 3;          // 0..2047
    const uint32_t d    = (half << 9) + threadIdx.x * 4u;

    // PE once per thread, pre-scaled by 1/0.9.
    const float KNEG   = -0.02595256324130752f;   // -log2(10000)/512
    const float STEP   = 0.98217188542871857f;    // 2^KNEG
    const float INV2PI = 0.15915494309189535f;
    const float TWOPI  = 6.2831853071795865f;
    const float INVKEEP = 1.0f / 0.9f;
    const float sf = (float)s;
    const float w0 = exp2f((float)(d >> 1) * KNEG) * INV2PI;
    const float w1 = w0 * STEP;
    float pe[4];
    {
        float t0 = sf * w0, t1 = sf * w1;
        float a0 = (t0 - rintf(t0)) * TWOPI;
        float a1 = (t1 - rintf(t1)) * TWOPI;
        pe[0] = __sinf(a0) * INVKEEP; pe[1] = __cosf(a0) * INVKEEP;
        pe[2] = __sinf(a1) * INVKEEP; pe[3] = __cosf(a1) * INVKEEP;
    }

    const uint32_t b0 = bp * 2u;
    const uint32_t jA = (b0 << 21) + (s << 10) + d;   // flat idx, batch b0
    const uint32_t jB = jA + (1u << 21);              // batch b0 + 1

    // Both gathers issued before the fused threefry (MLP = 2).
    const int tokA = __ldg(x + (b0 << 11) + s);
    const int tokB = __ldg(x + ((b0 + 1u) << 11) + s);
    const float4 eA = *reinterpret_cast<const float4*>(
        emb + ((size_t)tokA << 10) + d);
    const float4 eB = *reinterpret_cast<const float4*>(
        emb + ((size_t)tokB << 10) + d);

    uint32_t bits[8];
    tf_bits8(jA, jB, bits);

    float4 yA, yB;
    yA.x = (bits[0] < 0xE6666600u) ? fmaf(eA.x, INVKEEP, pe[0]) : 0.0f;
    yA.y = (bits[1] < 0xE6666600u) ? fmaf(eA.y, INVKEEP, pe[1]) : 0.0f;
    yA.z = (bits[2] < 0xE6666600u) ? fmaf(eA.z, INVKEEP, pe[2]) : 0.0f;
    yA.w = (bits[3] < 0xE6666600u) ? fmaf(eA.w, INVKEEP, pe[3]) : 0.0f;
    yB.x = (bits[4] < 0xE6666600u) ? fmaf(eB.x, INVKEEP, pe[0]) : 0.0f;
    yB.y = (bits[5] < 0xE6666600u) ? fmaf(eB.y, INVKEEP, pe[1]) : 0.0f;
    yB.z = (bits[6] < 0xE6666600u) ? fmaf(eB.z, INVKEEP, pe[2]) : 0.0f;
    yB.w = (bits[7] < 0xE6666600u) ? fmaf(eB.w, INVKEEP, pe[3]) : 0.0f;

    *reinterpret_cast<float4*>(out + jA) = yA;
    *reinterpret_cast<float4*>(out + jB) = yB;
}

extern "C" void kernel_launch(void* const* d_in, const int* in_sizes, int n_in,
                              void* d_out, int out_size) {
    const int* x;
    const float* emb;
    if (in_sizes[0] == 8 * 2048) {
        x = (const int*)d_in[0];
        emb = (const float*)d_in[1];
    } else {
        x = (const int*)d_in[1];
        emb = (const float*)d_in[0];
    }
    float* out = (float*)d_out;

    // 2048 s * 2 halves * 4 batch-pairs = 16384 blocks
    embed_pe_drop_kernel<<<16384, 128>>>(x, emb, out);
}